// round 9
// baseline (speedup 1.0000x reference)
#include <cuda_runtime.h>
#include <mma.h>
#include <cstdint>
using namespace nvcuda;

#define NMAX 200000
#define KOFF 27
#define TILE 128
#define LDA 40                             // A/C smem row stride (words)
#define BN_EPS 1e-3f

// ---------------- scratch (__device__ globals; no allocs allowed) ----------
__device__ __align__(256) float g_acc1[(size_t)NMAX * 32];
__device__ __align__(256) float g_acc2[(size_t)NMAX * 32];
__device__ __align__(256) float g_w1h[KOFF * 512],  g_w1l[KOFF * 512];
__device__ __align__(256) float g_w2h[KOFF * 1024], g_w2l[KOFF * 1024];
__device__ int   g_inv[(size_t)KOFF * NMAX];   // inv[k][dst] = src or -1
// [0:64) L1 sum/sumsq  [64:128) L2 sum/sumsq  [128:192) L1 sc/sh  [192:256) L2 sc/sh
__device__ float g_sums[256];

__device__ __forceinline__ float tf32r(float x) {
    uint32_t u; asm("cvt.rna.tf32.f32 %0, %1;" : "=r"(u) : "f"(x));
    return __uint_as_float(u);
}

// ---------------- inverse rulebook: inv[k][dst] = src ----------------------
__global__ void inv_k(const int* __restrict__ rin, const int* __restrict__ rout,
                      int n, int* __restrict__ inv) {
    int k = blockIdx.y;
    int p = blockIdx.x * blockDim.x + threadIdx.x;
    if (p >= n) return;
    int d = rout[(size_t)k * n + p];
    if (d < n) inv[(size_t)k * n + d] = rin[(size_t)k * n + p];
}

// ---------------- W hi/lo tf32 splits (row-major [k][ci][co]) --------------
__global__ void prepw_k(const float* __restrict__ W1, const float* __restrict__ W2) {
    int k = blockIdx.x;
    for (int t = threadIdx.x; t < 512; t += 256) {
        float v = W1[(size_t)k * 512 + t];
        float h = tf32r(v);
        g_w1h[k * 512 + t] = h;
        g_w1l[k * 512 + t] = tf32r(v - h);
    }
    for (int t = threadIdx.x; t < 1024; t += 256) {
        float v = W2[(size_t)k * 1024 + t];
        float h = tf32r(v);
        g_w2h[k * 1024 + t] = h;
        g_w2l[k * 1024 + t] = tf32r(v - h);
    }
}

// ---------------- conv: dense inv-gather + wmma tf32 3x-split --------------
// Block = 256 threads (8 warps) owns 128 dst rows; warp owns 16 rows.
// Per offset k: dense gather X[inv[k][r0+row]] (or 0) -> regs, hi/lo tf32
// split -> smem A[buf]; 8 warps run m16n16k8 tf32 MMAs (hi*hi+lo*hi+hi*lo),
// C fragments accumulate in registers across all 27 offsets. Double-buffered
// A, 1 barrier/offset; gather LDG latency hidden under MMA issue.
template <int KSTEPS, bool BNIN>
__global__ void __launch_bounds__(256) convmma_k(
    const float* __restrict__ X,
    const float* __restrict__ Wh, const float* __restrict__ Wl,
    const int* __restrict__ inv,
    float* __restrict__ out, int n, int statoff)
{
    const int CIN = KSTEPS * 8;            // 16 or 32
    const int CH  = CIN / 4;               // float4 chunks per row
    const int CSH = (KSTEPS == 4) ? 3 : 2;
    const int PF  = (TILE * CH) / 256;     // chunks per thread (2 or 4)
    const int WSZ = CIN * 32;

    extern __shared__ float sm[];
    float* AhiB = sm;                      // 2 * 5120
    float* AloB = sm + 10240;              // 2 * 5120
    float* bns  = sm + 20480;              // 64
    float* red  = sm + 20544;              // 512

    int tx = threadIdx.x;
    int wid = tx >> 5;
    int tile = blockIdx.x, r0 = tile * TILE;
    int nrows = n - r0; if (nrows > TILE) nrows = TILE;

    if (BNIN && tx < 64) bns[tx] = g_sums[128 + tx];
    __syncthreads();

    float4 gv[PF]; int gofs[PF];

    auto gload = [&](int k) {
        const int* invk = inv + (size_t)k * n + r0;
        #pragma unroll
        for (int i = 0; i < PF; i++) {
            int gi = tx + i * 256;
            int p = gi >> CSH, c4 = gi & (CH - 1);
            gofs[i] = p * LDA + c4 * 4;
            int src = (r0 + p < n) ? __ldg(invk + p) : -1;
            if (src >= 0) {
                float4 v = ((const float4*)(X + (size_t)src * CIN))[c4];
                if (BNIN) {
                    float4 sc = *(const float4*)&bns[c4 * 4];
                    float4 sh = *(const float4*)&bns[32 + c4 * 4];
                    v.x = fmaxf(fmaf(v.x, sc.x, sh.x), 0.f);
                    v.y = fmaxf(fmaf(v.y, sc.y, sh.y), 0.f);
                    v.z = fmaxf(fmaf(v.z, sc.z, sh.z), 0.f);
                    v.w = fmaxf(fmaf(v.w, sc.w, sh.w), 0.f);
                }
                gv[i] = v;
            } else gv[i] = make_float4(0.f, 0.f, 0.f, 0.f);
        }
    };
    auto gstore = [&](int j) {
        int b = j & 1;
        float* Ah = AhiB + b * 5120;
        float* Al = AloB + b * 5120;
        #pragma unroll
        for (int i = 0; i < PF; i++) {
            float4 v = gv[i], h, l;
            h.x = tf32r(v.x); l.x = tf32r(v.x - h.x);
            h.y = tf32r(v.y); l.y = tf32r(v.y - h.y);
            h.z = tf32r(v.z); l.z = tf32r(v.z - h.z);
            h.w = tf32r(v.w); l.w = tf32r(v.w - h.w);
            *(float4*)(Ah + gofs[i]) = h;
            *(float4*)(Al + gofs[i]) = l;
        }
    };

    wmma::fragment<wmma::accumulator, 16, 16, 8, float> cf[2];
    wmma::fill_fragment(cf[0], 0.f);
    wmma::fill_fragment(cf[1], 0.f);

    gload(0); gstore(0);
    __syncthreads();

    for (int j = 0; j < KOFF; j++) {
        int b = j & 1;
        if (j + 1 < KOFF) gload(j + 1);    // LDG latency hidden under MMA

        const float* Ah = AhiB + b * 5120 + wid * 16 * LDA;
        const float* Al = AloB + b * 5120 + wid * 16 * LDA;
        const float* wh = Wh + (size_t)j * WSZ;
        const float* wl = Wl + (size_t)j * WSZ;
        #pragma unroll
        for (int ks = 0; ks < KSTEPS; ks++) {
            wmma::fragment<wmma::matrix_a, 16, 16, 8, wmma::precision::tf32,
                           wmma::row_major> fah, fal;
            wmma::load_matrix_sync(fah, Ah + ks * 8, LDA);
            wmma::load_matrix_sync(fal, Al + ks * 8, LDA);
            #pragma unroll
            for (int nf = 0; nf < 2; nf++) {
                wmma::fragment<wmma::matrix_b, 16, 16, 8, wmma::precision::tf32,
                               wmma::row_major> fbh, fbl;
                wmma::load_matrix_sync(fbh, wh + ks * 8 * 32 + nf * 16, 32);
                wmma::load_matrix_sync(fbl, wl + ks * 8 * 32 + nf * 16, 32);
                wmma::mma_sync(cf[nf], fah, fbh, cf[nf]);
                wmma::mma_sync(cf[nf], fal, fbh, cf[nf]);
                wmma::mma_sync(cf[nf], fah, fbl, cf[nf]);
            }
        }

        if (j + 1 < KOFF) gstore(j + 1);   // writes buf^1 (sealed last barrier)
        __syncthreads();
    }

    // epilogue: C frags -> smem (reuse A region) -> coalesced store + stats
    float* C = sm;                          // stride LDA
    wmma::store_matrix_sync(C + wid * 16 * LDA,      cf[0], LDA, wmma::mem_row_major);
    wmma::store_matrix_sync(C + wid * 16 * LDA + 16, cf[1], LDA, wmma::mem_row_major);
    __syncthreads();

    for (int i = tx; i < nrows * 8; i += 256) {
        int row = i >> 3, co = i & 7;
        ((float4*)(out + (size_t)(r0 + row) * 32))[co] = *(float4*)&C[row * LDA + co * 4];
    }
    int ch = tx & 31, wg = tx >> 5;
    float s = 0.f, q = 0.f;
    for (int r = wg; r < nrows; r += 8) {
        float v = C[r * LDA + ch];
        s += v;
        q = fmaf(v, v, q);
    }
    red[tx] = s; red[256 + tx] = q;
    __syncthreads();
    if (tx < 32) {
        float S = 0.f, Q = 0.f;
        #pragma unroll
        for (int w = 0; w < 8; w++) { S += red[w * 32 + tx]; Q += red[256 + w * 32 + tx]; }
        atomicAdd(&g_sums[statoff + tx], S);
        atomicAdd(&g_sums[statoff + 32 + tx], Q);
    }
}

// ---------------- BN finalize ----------------------------------------------
__global__ void finalize_k(const float* __restrict__ gamma,
                           const float* __restrict__ beta,
                           int n, int off, int outoff) {
    int c = threadIdx.x;
    float inv_n = 1.f / (float)n;
    float mu  = g_sums[off + c] * inv_n;
    float var = g_sums[off + 32 + c] * inv_n - mu * mu;
    float sc  = gamma[c] * rsqrtf(var + BN_EPS);
    g_sums[outoff + c] = sc;
    g_sums[outoff + 32 + c] = beta[c] - mu * sc;
}

// ---------------- BN apply + ReLU (final output only) ----------------------
__global__ void apply_k(const float* __restrict__ in, float* __restrict__ out,
                        int n, int soff) {
    int total = n * 8;
    for (int i = blockIdx.x * blockDim.x + threadIdx.x; i < total;
         i += gridDim.x * blockDim.x) {
        int c4 = (i & 7) * 4;
        float4 v  = ((const float4*)in)[i];
        float4 sc = *(const float4*)&g_sums[soff + c4];
        float4 sh = *(const float4*)&g_sums[soff + 32 + c4];
        float4 o;
        o.x = fmaxf(fmaf(v.x, sc.x, sh.x), 0.f);
        o.y = fmaxf(fmaf(v.y, sc.y, sh.y), 0.f);
        o.z = fmaxf(fmaf(v.z, sc.z, sh.z), 0.f);
        o.w = fmaxf(fmaf(v.w, sc.w, sh.w), 0.f);
        ((float4*)out)[i] = o;
    }
}

// ---------------- launch ---------------------------------------------------
#define CONV_SMEM ((20480 + 64 + 512) * 4)

extern "C" void kernel_launch(void* const* d_in, const int* in_sizes, int n_in,
                              void* d_out, int out_size) {
    const float* feats  = (const float*)d_in[0];
    const float* W1     = (const float*)d_in[1];
    const float* gamma1 = (const float*)d_in[2];
    const float* beta1  = (const float*)d_in[3];
    const float* W2     = (const float*)d_in[4];
    const float* gamma2 = (const float*)d_in[5];
    const float* beta2  = (const float*)d_in[6];
    const int*   rin    = (const int*)d_in[7];
    const int*   rout   = (const int*)d_in[8];
    int n = in_sizes[0] / 16;

    float *acc1, *acc2, *w1h, *w1l, *w2h, *w2l, *sums;
    int* inv;
    cudaGetSymbolAddress((void**)&acc1, g_acc1);
    cudaGetSymbolAddress((void**)&acc2, g_acc2);
    cudaGetSymbolAddress((void**)&w1h, g_w1h);
    cudaGetSymbolAddress((void**)&w1l, g_w1l);
    cudaGetSymbolAddress((void**)&w2h, g_w2h);
    cudaGetSymbolAddress((void**)&w2l, g_w2l);
    cudaGetSymbolAddress((void**)&inv, g_inv);
    cudaGetSymbolAddress((void**)&sums, g_sums);

    cudaFuncSetAttribute(convmma_k<2, false>, cudaFuncAttributeMaxDynamicSharedMemorySize, CONV_SMEM);
    cudaFuncSetAttribute(convmma_k<4, true>,  cudaFuncAttributeMaxDynamicSharedMemorySize, CONV_SMEM);

    int tiles = (n + TILE - 1) / TILE;

    cudaMemsetAsync(inv, 0xFF, (size_t)KOFF * n * sizeof(int));   // all -1
    cudaMemsetAsync(sums, 0, 128 * sizeof(float));
    inv_k<<<dim3((n + 255) / 256, KOFF), 256>>>(rin, rout, n, inv);
    prepw_k<<<KOFF, 256>>>(W1, W2);

    convmma_k<2, false><<<tiles, 256, CONV_SMEM>>>(feats, w1h, w1l, inv, acc1, n, 0);
    finalize_k<<<1, 32>>>(gamma1, beta1, n, 0, 128);

    convmma_k<4, true><<<tiles, 256, CONV_SMEM>>>(acc1, w2h, w2l, inv, acc2, n, 64);
    finalize_k<<<1, 32>>>(gamma2, beta2, n, 64, 192);

    apply_k<<<1184, 256>>>(acc2, (float*)d_out, n, 192);
}

// round 11
// speedup vs baseline: 3.3577x; 3.3577x over previous
#include <cuda_runtime.h>

#define NMAX 200000
#define KOFF 27
#define TILE 128
#define TILESMAX ((NMAX + TILE - 1) / TILE)
#define SEGW (TILESMAX + 1)
#define BN_EPS 1e-3f

// ---------------- scratch (__device__ globals; no allocs allowed) ----------
__device__ __align__(256) float g_acc1[(size_t)NMAX * 32];
__device__ __align__(256) float g_acc2[(size_t)NMAX * 32];
__device__ int   g_seg[KOFF * SEGW];
// [0:64) L1 sum/sumsq  [64:128) L2 sum/sumsq  [128:192) L1 sc/sh  [192:256) L2 sc/sh
__device__ __align__(16) float g_sums[256];

// ---------------- seg: per (k, dst-tile) pair-range via binary search ------
__global__ void seg_k(const int* __restrict__ rout, int n, int tiles) {
    if (blockIdx.x == 0 && threadIdx.x < 128) g_sums[threadIdx.x] = 0.f;
    int idx = blockIdx.x * blockDim.x + threadIdx.x;
    int total = KOFF * (tiles + 1);
    if (idx >= total) return;
    int k = idx / (tiles + 1), t = idx % (tiles + 1);
    int target = t * TILE;
    if (target > n) target = n;
    const int* a = rout + (size_t)k * n;
    int lo = 0, hi = n;
    while (lo < hi) {
        int mid = (lo + hi) >> 1;
        if (a[mid] < target) lo = mid + 1; else hi = mid;
    }
    g_seg[k * SEGW + t] = lo;
}

// ==================== conv1: pipelined (R4 kernel, verbatim) ===============
template <int CIN, bool BNIN>
__global__ void __launch_bounds__(256) conv_k(
    const float* __restrict__ X, const float* __restrict__ W,
    const int* __restrict__ rin, const int* __restrict__ rout,
    float* __restrict__ out, int n, int statoff)
{
    const int AS  = CIN + 4;
    const int CH  = CIN / 4;
    const int CSH = (CIN == 32) ? 3 : 2;
    const int PF  = CH / 2;
    const int WF4 = CIN * 8;

    extern __shared__ float smem[];
    float* C    = smem;                            // 128*36
    float* AshB = C + 128 * 36;                    // 2 * 128*AS
    float* WshB = AshB + 2 * 128 * AS;             // 2 * CIN*32
    float* red  = WshB + 2 * CIN * 32;             // 512
    float* bns  = red + 512;                       // 64
    int*   dshB = (int*)(bns + 64);                // 2 * 128
    int*   klist = dshB + 256;
    int*   klo   = klist + KOFF;
    int*   kln   = klo + KOFF;
    int*   sst   = kln + KOFF;
    int*   sen   = sst + KOFF;
    int*   nk_sh = sen + KOFF;

    int tx = threadIdx.x;
    int tile = blockIdx.x;
    int r0 = tile * TILE;

    if (BNIN && tx < 64) bns[tx] = g_sums[128 + tx];
    if (tx < KOFF) { sst[tx] = g_seg[tx * SEGW + tile]; sen[tx] = g_seg[tx * SEGW + tile + 1]; }
    for (int i = tx; i < 128 * 36; i += 256) C[i] = 0.f;
    __syncthreads();
    if (tx == 0) {
        int m = 0;
        for (int k = 0; k < KOFF; k++) {
            int L = sen[k] - sst[k];
            if (L > 0) { klist[m] = k; klo[m] = sst[k]; kln[m] = L; m++; }
        }
        *nk_sh = m;
    }
    __syncthreads();
    int nk = *nk_sh;

    float4 pv[PF];
    float4 pw = make_float4(0.f, 0.f, 0.f, 0.f);
    int pdst = 0;
    int curL = 0;

    auto prefetch = [&](int j) {
        int k = klist[j], s = klo[j], L = kln[j];
        curL = L;
        const float4* Wk4 = (const float4*)(W + (size_t)k * CIN * 32);
        if (tx < WF4) pw = Wk4[tx];
        if (tx < L) pdst = __ldg(rout + (size_t)k * n + s + tx);
        #pragma unroll
        for (int i = 0; i < PF; i++) {
            int gi = tx + i * 256;
            int row = gi >> CSH, co = gi & (CH - 1);
            if (row < L) {
                int src = __ldg(rin + (size_t)k * n + s + row);
                float4 v = ((const float4*)(X + (size_t)src * CIN))[co];
                if (BNIN) {
                    float4 sc = *(const float4*)&bns[co * 4];
                    float4 sh = *(const float4*)&bns[32 + co * 4];
                    v.x = fmaxf(fmaf(v.x, sc.x, sh.x), 0.f);
                    v.y = fmaxf(fmaf(v.y, sc.y, sh.y), 0.f);
                    v.z = fmaxf(fmaf(v.z, sc.z, sh.z), 0.f);
                    v.w = fmaxf(fmaf(v.w, sc.w, sh.w), 0.f);
                }
                pv[i] = v;
            }
        }
    };

    if (nk > 0) prefetch(0);

    const int rg = tx >> 3, cg = tx & 7;
    const int rb = rg * 4;

    for (int idx = 0; idx < nk; idx++) {
        int buf = idx & 1;
        int L = curL;
        float* Ash = AshB + buf * 128 * AS;
        float* Wsh = WshB + buf * CIN * 32;
        int*   dsh = dshB + buf * 128;

        if (tx < WF4) ((float4*)Wsh)[tx] = pw;
        if (tx < L) dsh[tx] = pdst - r0;
        #pragma unroll
        for (int i = 0; i < PF; i++) {
            int gi = tx + i * 256;
            int row = gi >> CSH, co = gi & (CH - 1);
            if (row < L) *(float4*)&Ash[row * AS + co * 4] = pv[i];
        }
        __syncthreads();

        if (idx + 1 < nk) prefetch(idx + 1);

        if (rb < L) {
            float4 cc[4];
            #pragma unroll
            for (int i = 0; i < 4; i++) cc[i] = make_float4(0.f, 0.f, 0.f, 0.f);

            #pragma unroll
            for (int c4 = 0; c4 < CIN / 4; c4++) {
                int ci = c4 * 4;
                float4 a0 = *(const float4*)&Ash[(rb + 0) * AS + ci];
                float4 a1 = *(const float4*)&Ash[(rb + 1) * AS + ci];
                float4 a2 = *(const float4*)&Ash[(rb + 2) * AS + ci];
                float4 a3 = *(const float4*)&Ash[(rb + 3) * AS + ci];
                float4 w0 = *(const float4*)&Wsh[(ci + 0) * 32 + cg * 4];
                float4 w1 = *(const float4*)&Wsh[(ci + 1) * 32 + cg * 4];
                float4 w2 = *(const float4*)&Wsh[(ci + 2) * 32 + cg * 4];
                float4 w3 = *(const float4*)&Wsh[(ci + 3) * 32 + cg * 4];

                cc[0].x = fmaf(a0.x, w0.x, cc[0].x); cc[0].y = fmaf(a0.x, w0.y, cc[0].y);
                cc[0].z = fmaf(a0.x, w0.z, cc[0].z); cc[0].w = fmaf(a0.x, w0.w, cc[0].w);
                cc[1].x = fmaf(a1.x, w0.x, cc[1].x); cc[1].y = fmaf(a1.x, w0.y, cc[1].y);
                cc[1].z = fmaf(a1.x, w0.z, cc[1].z); cc[1].w = fmaf(a1.x, w0.w, cc[1].w);
                cc[2].x = fmaf(a2.x, w0.x, cc[2].x); cc[2].y = fmaf(a2.x, w0.y, cc[2].y);
                cc[2].z = fmaf(a2.x, w0.z, cc[2].z); cc[2].w = fmaf(a2.x, w0.w, cc[2].w);
                cc[3].x = fmaf(a3.x, w0.x, cc[3].x); cc[3].y = fmaf(a3.x, w0.y, cc[3].y);
                cc[3].z = fmaf(a3.x, w0.z, cc[3].z); cc[3].w = fmaf(a3.x, w0.w, cc[3].w);

                cc[0].x = fmaf(a0.y, w1.x, cc[0].x); cc[0].y = fmaf(a0.y, w1.y, cc[0].y);
                cc[0].z = fmaf(a0.y, w1.z, cc[0].z); cc[0].w = fmaf(a0.y, w1.w, cc[0].w);
                cc[1].x = fmaf(a1.y, w1.x, cc[1].x); cc[1].y = fmaf(a1.y, w1.y, cc[1].y);
                cc[1].z = fmaf(a1.y, w1.z, cc[1].z); cc[1].w = fmaf(a1.y, w1.w, cc[1].w);
                cc[2].x = fmaf(a2.y, w1.x, cc[2].x); cc[2].y = fmaf(a2.y, w1.y, cc[2].y);
                cc[2].z = fmaf(a2.y, w1.z, cc[2].z); cc[2].w = fmaf(a2.y, w1.w, cc[2].w);
                cc[3].x = fmaf(a3.y, w1.x, cc[3].x); cc[3].y = fmaf(a3.y, w1.y, cc[3].y);
                cc[3].z = fmaf(a3.y, w1.z, cc[3].z); cc[3].w = fmaf(a3.y, w1.w, cc[3].w);

                cc[0].x = fmaf(a0.z, w2.x, cc[0].x); cc[0].y = fmaf(a0.z, w2.y, cc[0].y);
                cc[0].z = fmaf(a0.z, w2.z, cc[0].z); cc[0].w = fmaf(a0.z, w2.w, cc[0].w);
                cc[1].x = fmaf(a1.z, w2.x, cc[1].x); cc[1].y = fmaf(a1.z, w2.y, cc[1].y);
                cc[1].z = fmaf(a1.z, w2.z, cc[1].z); cc[1].w = fmaf(a1.z, w2.w, cc[1].w);
                cc[2].x = fmaf(a2.z, w2.x, cc[2].x); cc[2].y = fmaf(a2.z, w2.y, cc[2].y);
                cc[2].z = fmaf(a2.z, w2.z, cc[2].z); cc[2].w = fmaf(a2.z, w2.w, cc[2].w);
                cc[3].x = fmaf(a3.z, w2.x, cc[3].x); cc[3].y = fmaf(a3.z, w2.y, cc[3].y);
                cc[3].z = fmaf(a3.z, w2.z, cc[3].z); cc[3].w = fmaf(a3.z, w2.w, cc[3].w);

                cc[0].x = fmaf(a0.w, w3.x, cc[0].x); cc[0].y = fmaf(a0.w, w3.y, cc[0].y);
                cc[0].z = fmaf(a0.w, w3.z, cc[0].z); cc[0].w = fmaf(a0.w, w3.w, cc[0].w);
                cc[1].x = fmaf(a1.w, w3.x, cc[1].x); cc[1].y = fmaf(a1.w, w3.y, cc[1].y);
                cc[1].z = fmaf(a1.w, w3.z, cc[1].z); cc[1].w = fmaf(a1.w, w3.w, cc[1].w);
                cc[2].x = fmaf(a2.w, w3.x, cc[2].x); cc[2].y = fmaf(a2.w, w3.y, cc[2].y);
                cc[2].z = fmaf(a2.w, w3.z, cc[2].z); cc[2].w = fmaf(a2.w, w3.w, cc[2].w);
                cc[3].x = fmaf(a3.w, w3.x, cc[3].x); cc[3].y = fmaf(a3.w, w3.y, cc[3].y);
                cc[3].z = fmaf(a3.w, w3.z, cc[3].z); cc[3].w = fmaf(a3.w, w3.w, cc[3].w);
            }

            #pragma unroll
            for (int i = 0; i < 4; i++) {
                int row = rb + i;
                if (row < L) {
                    float* p = &C[dsh[row] * 36 + cg * 4];
                    float4 cv = *(float4*)p;
                    cv.x += cc[i].x; cv.y += cc[i].y;
                    cv.z += cc[i].z; cv.w += cc[i].w;
                    *(float4*)p = cv;
                }
            }
        }
    }
    __syncthreads();

    int nrows = n - r0; if (nrows > 128) nrows = 128;
    for (int i = tx; i < nrows * 8; i += 256) {
        int row = i >> 3, co = i & 7;
        ((float4*)(out + (size_t)(r0 + row) * 32))[co] = *(float4*)&C[row * 36 + co * 4];
    }
    int ch = tx & 31, rb2 = tx >> 5;
    float s = 0.f, q = 0.f;
    for (int r = rb2; r < nrows; r += 8) {
        float v = C[r * 36 + ch];
        s += v;
        q = fmaf(v, v, q);
    }
    red[tx] = s; red[256 + tx] = q;
    __syncthreads();
    if (tx < 32) {
        float S = 0.f, Q = 0.f;
        #pragma unroll
        for (int w = 0; w < 8; w++) { S += red[w * 32 + tx]; Q += red[256 + w * 32 + tx]; }
        atomicAdd(&g_sums[statoff + tx], S);
        atomicAdd(&g_sums[statoff + 32 + tx], Q);
    }
}

// ==================== conv2: simple double-barrier (R3 kernel, aligned) ====
__global__ void __launch_bounds__(256) conv2s_k(
    const float* __restrict__ X, const float* __restrict__ W,
    const int* __restrict__ rin, const int* __restrict__ rout,
    float* __restrict__ out, int n, int statoff)
{
    const int CIN = 32;
    const int AS = CIN + 4;               // 36
    const int CH = CIN / 4;               // 8
    const int CSH = 3;
    __shared__ __align__(16) float C[128 * 36];
    __shared__ __align__(16) float Ash[128 * 36];
    __shared__ __align__(16) float Wsh[CIN * 32];
    __shared__ __align__(16) float red[512];
    __shared__ __align__(16) float bns[64];
    __shared__ __align__(16) int   dsh[128];
    __shared__ __align__(16) int   ssh[28];
    __shared__ __align__(16) int   esh[28];

    int tx = threadIdx.x;
    int tile = blockIdx.x;
    int r0 = tile * TILE;

    if (tx < 64) bns[tx] = g_sums[128 + tx];
    if (tx < KOFF) { ssh[tx] = g_seg[tx * SEGW + tile]; esh[tx] = g_seg[tx * SEGW + tile + 1]; }
    for (int i = tx; i < 128 * 36; i += 256) C[i] = 0.f;
    __syncthreads();

    const int rg = tx >> 3, cg = tx & 7;
    const int rb = rg * 4;

    for (int k = 0; k < KOFF; k++) {
        int s = ssh[k];
        int L = esh[k] - s;
        if (L == 0) continue;             // uniform across block: safe

        __syncthreads();                  // prev compute done before restage

        const float4* Wk4 = (const float4*)(W + (size_t)k * CIN * 32);
        #pragma unroll
        for (int i = tx; i < CIN * 8; i += 256) ((float4*)Wsh)[i] = Wk4[i];

        if (tx < L) dsh[tx] = __ldg(rout + (size_t)k * n + s + tx) - r0;
        for (int i = tx; i < L * CH; i += 256) {
            int row = i >> CSH, co = i & (CH - 1);
            int src = __ldg(rin + (size_t)k * n + s + row);
            float4 v = ((const float4*)(X + (size_t)src * CIN))[co];
            float4 sc = *(const float4*)&bns[co * 4];
            float4 sh = *(const float4*)&bns[32 + co * 4];
            v.x = fmaxf(fmaf(v.x, sc.x, sh.x), 0.f);
            v.y = fmaxf(fmaf(v.y, sc.y, sh.y), 0.f);
            v.z = fmaxf(fmaf(v.z, sc.z, sh.z), 0.f);
            v.w = fmaxf(fmaf(v.w, sc.w, sh.w), 0.f);
            *(float4*)&Ash[row * AS + co * 4] = v;
        }
        __syncthreads();

        if (rb < L) {
            float4 cc[4];
            #pragma unroll
            for (int i = 0; i < 4; i++) cc[i] = make_float4(0.f, 0.f, 0.f, 0.f);

            #pragma unroll
            for (int c4 = 0; c4 < CIN / 4; c4++) {
                int ci = c4 * 4;
                float4 a0 = *(const float4*)&Ash[(rb + 0) * AS + ci];
                float4 a1 = *(const float4*)&Ash[(rb + 1) * AS + ci];
                float4 a2 = *(const float4*)&Ash[(rb + 2) * AS + ci];
                float4 a3 = *(const float4*)&Ash[(rb + 3) * AS + ci];
                float4 w0 = *(const float4*)&Wsh[(ci + 0) * 32 + cg * 4];
                float4 w1 = *(const float4*)&Wsh[(ci + 1) * 32 + cg * 4];
                float4 w2 = *(const float4*)&Wsh[(ci + 2) * 32 + cg * 4];
                float4 w3 = *(const float4*)&Wsh[(ci + 3) * 32 + cg * 4];

                cc[0].x = fmaf(a0.x, w0.x, cc[0].x); cc[0].y = fmaf(a0.x, w0.y, cc[0].y);
                cc[0].z = fmaf(a0.x, w0.z, cc[0].z); cc[0].w = fmaf(a0.x, w0.w, cc[0].w);
                cc[1].x = fmaf(a1.x, w0.x, cc[1].x); cc[1].y = fmaf(a1.x, w0.y, cc[1].y);
                cc[1].z = fmaf(a1.x, w0.z, cc[1].z); cc[1].w = fmaf(a1.x, w0.w, cc[1].w);
                cc[2].x = fmaf(a2.x, w0.x, cc[2].x); cc[2].y = fmaf(a2.x, w0.y, cc[2].y);
                cc[2].z = fmaf(a2.x, w0.z, cc[2].z); cc[2].w = fmaf(a2.x, w0.w, cc[2].w);
                cc[3].x = fmaf(a3.x, w0.x, cc[3].x); cc[3].y = fmaf(a3.x, w0.y, cc[3].y);
                cc[3].z = fmaf(a3.x, w0.z, cc[3].z); cc[3].w = fmaf(a3.x, w0.w, cc[3].w);

                cc[0].x = fmaf(a0.y, w1.x, cc[0].x); cc[0].y = fmaf(a0.y, w1.y, cc[0].y);
                cc[0].z = fmaf(a0.y, w1.z, cc[0].z); cc[0].w = fmaf(a0.y, w1.w, cc[0].w);
                cc[1].x = fmaf(a1.y, w1.x, cc[1].x); cc[1].y = fmaf(a1.y, w1.y, cc[1].y);
                cc[1].z = fmaf(a1.y, w1.z, cc[1].z); cc[1].w = fmaf(a1.y, w1.w, cc[1].w);
                cc[2].x = fmaf(a2.y, w1.x, cc[2].x); cc[2].y = fmaf(a2.y, w1.y, cc[2].y);
                cc[2].z = fmaf(a2.y, w1.z, cc[2].z); cc[2].w = fmaf(a2.y, w1.w, cc[2].w);
                cc[3].x = fmaf(a3.y, w1.x, cc[3].x); cc[3].y = fmaf(a3.y, w1.y, cc[3].y);
                cc[3].z = fmaf(a3.y, w1.z, cc[3].z); cc[3].w = fmaf(a3.y, w1.w, cc[3].w);

                cc[0].x = fmaf(a0.z, w2.x, cc[0].x); cc[0].y = fmaf(a0.z, w2.y, cc[0].y);
                cc[0].z = fmaf(a0.z, w2.z, cc[0].z); cc[0].w = fmaf(a0.z, w2.w, cc[0].w);
                cc[1].x = fmaf(a1.z, w2.x, cc[1].x); cc[1].y = fmaf(a1.z, w2.y, cc[1].y);
                cc[1].z = fmaf(a1.z, w2.z, cc[1].z); cc[1].w = fmaf(a1.z, w2.w, cc[1].w);
                cc[2].x = fmaf(a2.z, w2.x, cc[2].x); cc[2].y = fmaf(a2.z, w2.y, cc[2].y);
                cc[2].z = fmaf(a2.z, w2.z, cc[2].z); cc[2].w = fmaf(a2.z, w2.w, cc[2].w);
                cc[3].x = fmaf(a3.z, w2.x, cc[3].x); cc[3].y = fmaf(a3.z, w2.y, cc[3].y);
                cc[3].z = fmaf(a3.z, w2.z, cc[3].z); cc[3].w = fmaf(a3.z, w2.w, cc[3].w);

                cc[0].x = fmaf(a0.w, w3.x, cc[0].x); cc[0].y = fmaf(a0.w, w3.y, cc[0].y);
                cc[0].z = fmaf(a0.w, w3.z, cc[0].z); cc[0].w = fmaf(a0.w, w3.w, cc[0].w);
                cc[1].x = fmaf(a1.w, w3.x, cc[1].x); cc[1].y = fmaf(a1.w, w3.y, cc[1].y);
                cc[1].z = fmaf(a1.w, w3.z, cc[1].z); cc[1].w = fmaf(a1.w, w3.w, cc[1].w);
                cc[2].x = fmaf(a2.w, w3.x, cc[2].x); cc[2].y = fmaf(a2.w, w3.y, cc[2].y);
                cc[2].z = fmaf(a2.w, w3.z, cc[2].z); cc[2].w = fmaf(a2.w, w3.w, cc[2].w);
                cc[3].x = fmaf(a3.w, w3.x, cc[3].x); cc[3].y = fmaf(a3.w, w3.y, cc[3].y);
                cc[3].z = fmaf(a3.w, w3.z, cc[3].z); cc[3].w = fmaf(a3.w, w3.w, cc[3].w);
            }

            #pragma unroll
            for (int i = 0; i < 4; i++) {
                int row = rb + i;
                if (row < L) {
                    float* p = &C[dsh[row] * 36 + cg * 4];   // unique dst: race-free
                    float4 cv = *(float4*)p;
                    cv.x += cc[i].x; cv.y += cc[i].y;
                    cv.z += cc[i].z; cv.w += cc[i].w;
                    *(float4*)p = cv;
                }
            }
        }
    }
    __syncthreads();

    int nrows = n - r0; if (nrows > 128) nrows = 128;
    for (int i = tx; i < nrows * 8; i += 256) {
        int row = i >> 3, co = i & 7;
        ((float4*)(out + (size_t)(r0 + row) * 32))[co] = *(float4*)&C[row * 36 + co * 4];
    }
    int ch = tx & 31, rb2 = tx >> 5;
    float s = 0.f, q = 0.f;
    for (int r = rb2; r < nrows; r += 8) {
        float v = C[r * 36 + ch];
        s += v;
        q = fmaf(v, v, q);
    }
    red[tx] = s; red[256 + tx] = q;
    __syncthreads();
    if (tx < 32) {
        float S = 0.f, Q = 0.f;
        #pragma unroll
        for (int w = 0; w < 8; w++) { S += red[w * 32 + tx]; Q += red[256 + w * 32 + tx]; }
        atomicAdd(&g_sums[statoff + tx], S);
        atomicAdd(&g_sums[statoff + 32 + tx], Q);
    }
}

// ---------------- BN finalize ----------------------------------------------
__global__ void finalize_k(const float* __restrict__ gamma,
                           const float* __restrict__ beta,
                           int n, int off, int outoff) {
    int c = threadIdx.x;
    float inv_n = 1.f / (float)n;
    float mu  = g_sums[off + c] * inv_n;
    float var = g_sums[off + 32 + c] * inv_n - mu * mu;
    float sc  = gamma[c] * rsqrtf(var + BN_EPS);
    g_sums[outoff + c] = sc;
    g_sums[outoff + 32 + c] = beta[c] - mu * sc;
}

// ---------------- BN apply + ReLU (final output only) ----------------------
__global__ void apply_k(const float* __restrict__ in, float* __restrict__ out,
                        int n, int soff) {
    int total = n * 8;
    for (int i = blockIdx.x * blockDim.x + threadIdx.x; i < total;
         i += gridDim.x * blockDim.x) {
        int c4 = (i & 7) * 4;
        float4 v  = ((const float4*)in)[i];
        float4 sc = *(const float4*)&g_sums[soff + c4];
        float4 sh = *(const float4*)&g_sums[soff + 32 + c4];
        float4 o;
        o.x = fmaxf(fmaf(v.x, sc.x, sh.x), 0.f);
        o.y = fmaxf(fmaf(v.y, sc.y, sh.y), 0.f);
        o.z = fmaxf(fmaf(v.z, sc.z, sh.z), 0.f);
        o.w = fmaxf(fmaf(v.w, sc.w, sh.w), 0.f);
        ((float4*)out)[i] = o;
    }
}

// ---------------- launch ---------------------------------------------------
static int conv1_smem_bytes() {
    int fl = 128 * 36 + 2 * 128 * 20 + 2 * 16 * 32 + 512 + 64;
    int in = 2 * 128 + KOFF * 5 + 1;
    return (fl + in) * 4 + 16;
}

extern "C" void kernel_launch(void* const* d_in, const int* in_sizes, int n_in,
                              void* d_out, int out_size) {
    const float* feats  = (const float*)d_in[0];
    const float* W1     = (const float*)d_in[1];
    const float* gamma1 = (const float*)d_in[2];
    const float* beta1  = (const float*)d_in[3];
    const float* W2     = (const float*)d_in[4];
    const float* gamma2 = (const float*)d_in[5];
    const float* beta2  = (const float*)d_in[6];
    const int*   rin    = (const int*)d_in[7];
    const int*   rout   = (const int*)d_in[8];
    int n = in_sizes[0] / 16;

    float *acc1, *acc2;
    cudaGetSymbolAddress((void**)&acc1, g_acc1);
    cudaGetSymbolAddress((void**)&acc2, g_acc2);

    int smem1 = conv1_smem_bytes();
    cudaFuncSetAttribute(conv_k<16, false>, cudaFuncAttributeMaxDynamicSharedMemorySize, smem1);

    int tiles = (n + TILE - 1) / TILE;
    int segthreads = KOFF * (tiles + 1);

    seg_k<<<(segthreads + 255) / 256, 256>>>(rout, n, tiles);

    conv_k<16, false><<<tiles, 256, smem1>>>(feats, W1, rin, rout, acc1, n, 0);
    finalize_k<<<1, 32>>>(gamma1, beta1, n, 0, 128);

    conv2s_k<<<tiles, 256>>>(acc1, W2, rin, rout, acc2, n, 64);
    finalize_k<<<1, 32>>>(gamma2, beta2, n, 64, 192);

    apply_k<<<1184, 256>>>(acc2, (float*)d_out, n, 192);
}